// round 1
// baseline (speedup 1.0000x reference)
#include <cuda_runtime.h>

#define BB 4
#define TT 4096
#define CC 512
#define HH 64

#define NEG_BIG (-1e30f)

// Scratch: q, k, v projections [B, T, H]  (12 MB total, static device arrays)
__device__ float g_q[BB * TT * HH];
__device__ float g_k[BB * TT * HH];
__device__ float g_v[BB * TT * HH];
__device__ int   g_ctr;   // dynamic tile scheduler counter (reset by proj kernel)

// ---------------------------------------------------------------------------
// Kernel 1: fused QKV projection.
// One block computes 64 rows of q,k,v (all 64 output dims each).
// Thread layout 16x16, each thread owns a 4x4 register tile per weight.
// ---------------------------------------------------------------------------
__global__ __launch_bounds__(256) void proj_kernel(
    const float* __restrict__ x,
    const float* __restrict__ Wq, const float* __restrict__ bq,
    const float* __restrict__ Wk, const float* __restrict__ bk,
    const float* __restrict__ Wv, const float* __restrict__ bv)
{
    if (blockIdx.x == 0 && threadIdx.x == 0) g_ctr = 0;  // reset scheduler

    __shared__ float x_s[64 * 64];
    __shared__ float w_s[64 * 64];

    const int tid = threadIdx.x;
    const int ty  = tid >> 4;       // 0..15 (row group)
    const int tx  = tid & 15;       // 0..15 (col group)
    const int m0  = blockIdx.x * 64;

    float acc[3][4][4];
#pragma unroll
    for (int w = 0; w < 3; w++)
#pragma unroll
        for (int i = 0; i < 4; i++)
#pragma unroll
            for (int j = 0; j < 4; j++) acc[w][i][j] = 0.0f;

    for (int kc = 0; kc < CC / 64; kc++) {
        __syncthreads();  // previous chunk's compute done before overwriting x_s
        // load x chunk [64 rows][64 k] (coalesced float4)
#pragma unroll
        for (int i = 0; i < 4; i++) {
            int idx = i * 256 + tid;
            int r = idx >> 4, c4 = idx & 15;
            ((float4*)x_s)[idx] =
                *(const float4*)(x + (m0 + r) * CC + kc * 64 + c4 * 4);
        }
#pragma unroll
        for (int w = 0; w < 3; w++) {
            const float* W = (w == 0) ? Wq : (w == 1) ? Wk : Wv;
            __syncthreads();  // prev weight's compute done (and x_s stored, for w==0 with next sync)
            const float4* wt = (const float4*)(W + kc * 64 * HH);  // contiguous 64x64 tile
#pragma unroll
            for (int i = 0; i < 4; i++) ((float4*)w_s)[i * 256 + tid] = wt[i * 256 + tid];
            __syncthreads();
#pragma unroll
            for (int k4 = 0; k4 < 16; k4++) {
                float a[4][4], bvv[4][4];
#pragma unroll
                for (int i = 0; i < 4; i++) {
                    float4 t = ((const float4*)x_s)[(ty * 4 + i) * 16 + k4];
                    a[i][0] = t.x; a[i][1] = t.y; a[i][2] = t.z; a[i][3] = t.w;
                }
#pragma unroll
                for (int c = 0; c < 4; c++) {
                    float4 t = ((const float4*)w_s)[(k4 * 4 + c) * 16 + tx];
                    bvv[c][0] = t.x; bvv[c][1] = t.y; bvv[c][2] = t.z; bvv[c][3] = t.w;
                }
#pragma unroll
                for (int i = 0; i < 4; i++)
#pragma unroll
                    for (int c = 0; c < 4; c++)
#pragma unroll
                        for (int j = 0; j < 4; j++)
                            acc[w][i][j] += a[i][c] * bvv[c][j];
            }
        }
    }

    // epilogue: add bias, store q/k/v
    float4 bqv = *(const float4*)(bq + tx * 4);
    float4 bkv = *(const float4*)(bk + tx * 4);
    float4 bvv4 = *(const float4*)(bv + tx * 4);
#pragma unroll
    for (int i = 0; i < 4; i++) {
        int row = m0 + ty * 4 + i;          // global row in [B*T)
        float4 r;
        r.x = acc[0][i][0] + bqv.x; r.y = acc[0][i][1] + bqv.y;
        r.z = acc[0][i][2] + bqv.z; r.w = acc[0][i][3] + bqv.w;
        *(float4*)(g_q + row * HH + tx * 4) = r;
        r.x = acc[1][i][0] + bkv.x; r.y = acc[1][i][1] + bkv.y;
        r.z = acc[1][i][2] + bkv.z; r.w = acc[1][i][3] + bkv.w;
        *(float4*)(g_k + row * HH + tx * 4) = r;
        r.x = acc[2][i][0] + bvv4.x; r.y = acc[2][i][1] + bvv4.y;
        r.z = acc[2][i][2] + bvv4.z; r.w = acc[2][i][3] + bvv4.w;
        *(float4*)(g_v + row * HH + tx * 4) = r;
    }
}

// ---------------------------------------------------------------------------
// Kernel 2: causal flash attention, fp32, online softmax.
// Dynamic scheduler: CTAs pull (b, q_tile) tasks in descending-work order.
// Per task: Q tile 64x64 (pre-scaled by 1/8), loop key tiles 0..qt.
// smem: q_s [row][d], kp_s = K^T [d][key] (reused to hold P [row][key]), v_s [key][d].
// Thread layout 16x16, each thread: 4x4 of S/P and 4x4 of O.
// ---------------------------------------------------------------------------
__global__ __launch_bounds__(256) void attn_kernel(
    const unsigned char* __restrict__ pmask,  // [B,T] bool over keys
    float* __restrict__ out)                  // [B,T,H]
{
    __shared__ float q_s[64 * 64];
    __shared__ float kp_s[64 * 64];   // K^T, then P
    __shared__ float v_s[64 * 64];
    __shared__ int   s_task;

    const int tid = threadIdx.x;
    const int ty  = tid >> 4;
    const int tx  = tid & 15;

    while (true) {
        __syncthreads();  // all prior smem reads done; s_task reusable
        if (tid == 0) s_task = atomicAdd(&g_ctr, 1);
        __syncthreads();
        int task = s_task;
        if (task >= 64 * BB) break;

        // descending q-tile order: heaviest tasks scheduled first
        int qt = 63 - (task >> 2);
        int b  = task & 3;

        // load Q tile, pre-scaled by 1/sqrt(H) = 0.125
        const float4* qb4 = (const float4*)(g_q + (b * TT + qt * 64) * HH);
#pragma unroll
        for (int i = 0; i < 4; i++) {
            float4 v = qb4[i * 256 + tid];
            v.x *= 0.125f; v.y *= 0.125f; v.z *= 0.125f; v.w *= 0.125f;
            ((float4*)q_s)[i * 256 + tid] = v;
        }

        float o[4][4];
        float m[4], l[4];
#pragma unroll
        for (int i = 0; i < 4; i++) {
            m[i] = NEG_BIG; l[i] = 0.0f;
#pragma unroll
            for (int j = 0; j < 4; j++) o[i][j] = 0.0f;
        }

        for (int kt = 0; kt <= qt; kt++) {
            __syncthreads();  // prior tile's P/V reads done; q_s store visible (first iter)

            // --- load K tile transposed: kp_s[d][key] (4x4 register transpose) ---
            {
                const float* kb = g_k + (b * TT + kt * 64) * HH;
                int kg = tid & 15;   // key group
                int dg = tid >> 4;   // d group
                float t4[4][4];
#pragma unroll
                for (int r = 0; r < 4; r++) {
                    float4 t = *(const float4*)(kb + (kg * 4 + r) * HH + dg * 4);
                    t4[r][0] = t.x; t4[r][1] = t.y; t4[r][2] = t.z; t4[r][3] = t.w;
                }
#pragma unroll
                for (int c = 0; c < 4; c++) {
                    float4 col;
                    col.x = t4[0][c]; col.y = t4[1][c]; col.z = t4[2][c]; col.w = t4[3][c];
                    ((float4*)kp_s)[(dg * 4 + c) * 16 + kg] = col;
                }
            }
            // --- load V tile (contiguous copy) ---
            {
                const float4* vb4 = (const float4*)(g_v + (b * TT + kt * 64) * HH);
#pragma unroll
                for (int i = 0; i < 4; i++)
                    ((float4*)v_s)[i * 256 + tid] = vb4[i * 256 + tid];
            }
            __syncthreads();

            // --- S = Q K^T (already scaled via Q) ---
            float s[4][4];
#pragma unroll
            for (int i = 0; i < 4; i++)
#pragma unroll
                for (int j = 0; j < 4; j++) s[i][j] = 0.0f;
#pragma unroll
            for (int d4 = 0; d4 < 16; d4++) {
                float a[4][4], kv[4][4];
#pragma unroll
                for (int i = 0; i < 4; i++) {
                    float4 t = ((const float4*)q_s)[(ty * 4 + i) * 16 + d4];
                    a[i][0] = t.x; a[i][1] = t.y; a[i][2] = t.z; a[i][3] = t.w;
                }
#pragma unroll
                for (int c = 0; c < 4; c++) {
                    float4 t = ((const float4*)kp_s)[(d4 * 4 + c) * 16 + tx];
                    kv[c][0] = t.x; kv[c][1] = t.y; kv[c][2] = t.z; kv[c][3] = t.w;
                }
#pragma unroll
                for (int i = 0; i < 4; i++)
#pragma unroll
                    for (int c = 0; c < 4; c++)
#pragma unroll
                        for (int j = 0; j < 4; j++)
                            s[i][j] += a[i][c] * kv[c][j];
            }

            // --- padding mask over keys ---
            {
                uchar4 pm = *(const uchar4*)(pmask + b * TT + kt * 64 + tx * 4);
                unsigned char pb[4] = {pm.x, pm.y, pm.z, pm.w};
#pragma unroll
                for (int j = 0; j < 4; j++)
                    if (pb[j]) {
#pragma unroll
                        for (int i = 0; i < 4; i++) s[i][j] = NEG_BIG;
                    }
            }
            // --- causal mask (diagonal tile only) ---
            if (kt == qt) {
#pragma unroll
                for (int i = 0; i < 4; i++)
#pragma unroll
                    for (int j = 0; j < 4; j++)
                        if (tx * 4 + j > ty * 4 + i) s[i][j] = NEG_BIG;
            }

            // --- online softmax update (row reductions across the 16 tx lanes) ---
#pragma unroll
            for (int i = 0; i < 4; i++) {
                float mx = fmaxf(fmaxf(s[i][0], s[i][1]), fmaxf(s[i][2], s[i][3]));
                mx = fmaxf(mx, __shfl_xor_sync(0xffffffffu, mx, 1));
                mx = fmaxf(mx, __shfl_xor_sync(0xffffffffu, mx, 2));
                mx = fmaxf(mx, __shfl_xor_sync(0xffffffffu, mx, 4));
                mx = fmaxf(mx, __shfl_xor_sync(0xffffffffu, mx, 8));
                float mn = fmaxf(m[i], mx);
                float alpha = __expf(m[i] - mn);
                m[i] = mn;
                float ps = 0.0f;
#pragma unroll
                for (int j = 0; j < 4; j++) {
                    float p = __expf(s[i][j] - mn);
                    s[i][j] = p;
                    ps += p;
                }
                ps += __shfl_xor_sync(0xffffffffu, ps, 1);
                ps += __shfl_xor_sync(0xffffffffu, ps, 2);
                ps += __shfl_xor_sync(0xffffffffu, ps, 4);
                ps += __shfl_xor_sync(0xffffffffu, ps, 8);
                l[i] = l[i] * alpha + ps;
#pragma unroll
                for (int j = 0; j < 4; j++) o[i][j] *= alpha;
            }

            __syncthreads();  // done reading K^T from kp_s
            // --- store P into kp_s [row][key] ---
#pragma unroll
            for (int i = 0; i < 4; i++) {
                float4 t;
                t.x = s[i][0]; t.y = s[i][1]; t.z = s[i][2]; t.w = s[i][3];
                ((float4*)kp_s)[(ty * 4 + i) * 16 + tx] = t;
            }
            __syncthreads();

            // --- O += P @ V ---
#pragma unroll
            for (int n4 = 0; n4 < 16; n4++) {
                float p[4][4], vv[4][4];
#pragma unroll
                for (int i = 0; i < 4; i++) {
                    float4 t = ((const float4*)kp_s)[(ty * 4 + i) * 16 + n4];
                    p[i][0] = t.x; p[i][1] = t.y; p[i][2] = t.z; p[i][3] = t.w;
                }
#pragma unroll
                for (int c = 0; c < 4; c++) {
                    float4 t = ((const float4*)v_s)[(n4 * 4 + c) * 16 + tx];
                    vv[c][0] = t.x; vv[c][1] = t.y; vv[c][2] = t.z; vv[c][3] = t.w;
                }
#pragma unroll
                for (int i = 0; i < 4; i++)
#pragma unroll
                    for (int c = 0; c < 4; c++)
#pragma unroll
                        for (int j = 0; j < 4; j++)
                            o[i][j] += p[i][c] * vv[c][j];
            }
        }

        // --- epilogue: normalize and write out ---
        float* ob = out + (b * TT + qt * 64) * HH;
#pragma unroll
        for (int i = 0; i < 4; i++) {
            float inv = 1.0f / l[i];
            float4 r;
            r.x = o[i][0] * inv; r.y = o[i][1] * inv;
            r.z = o[i][2] * inv; r.w = o[i][3] * inv;
            *(float4*)(ob + (ty * 4 + i) * HH + tx * 4) = r;
        }
    }
}

// ---------------------------------------------------------------------------
extern "C" void kernel_launch(void* const* d_in, const int* in_sizes, int n_in,
                              void* d_out, int out_size)
{
    const float*         x     = (const float*)d_in[0];
    const unsigned char* pmask = (const unsigned char*)d_in[1];
    const float*         Wq    = (const float*)d_in[2];
    const float*         bq    = (const float*)d_in[3];
    const float*         Wk    = (const float*)d_in[4];
    const float*         bk    = (const float*)d_in[5];
    const float*         Wv    = (const float*)d_in[6];
    const float*         bv    = (const float*)d_in[7];

    proj_kernel<<<(BB * TT) / 64, 256>>>(x, Wq, bq, Wk, bk, Wv, bv);
    attn_kernel<<<296, 256>>>(pmask, (float*)d_out);
}

// round 5
// speedup vs baseline: 1.8209x; 1.8209x over previous
#include <cuda_runtime.h>

#define BB 4
#define TT 4096
#define CC 512
#define HH 64

#define NEG_BIG (-1e30f)

// Units: chunk = up to 4 key-tiles (256 keys). Per batch: sum_qt (qt/4+1) = 544.
#define UNITS_PER_B 544
#define NUM_UNITS   (UNITS_PER_B * BB)   // 2176

// Scratch
__device__ float g_q[BB * TT * HH];
__device__ float g_k[BB * TT * HH];
__device__ float g_v[BB * TT * HH];
__device__ float g_pO[NUM_UNITS * 64 * 64];   // partial (unnormalized) O
__device__ float g_pm[NUM_UNITS * 64];        // partial row max
__device__ float g_pl[NUM_UNITS * 64];        // partial row sum
__device__ int   g_ctr;

// ---------------------------------------------------------------------------
// Kernel 1: fused QKV projection.
// ---------------------------------------------------------------------------
__global__ __launch_bounds__(256) void proj_kernel(
    const float* __restrict__ x,
    const float* __restrict__ Wq, const float* __restrict__ bq,
    const float* __restrict__ Wk, const float* __restrict__ bk,
    const float* __restrict__ Wv, const float* __restrict__ bv)
{
    if (blockIdx.x == 0 && threadIdx.x == 0) g_ctr = 0;  // reset scheduler

    __shared__ float x_s[64 * 64];
    __shared__ float w_s[64 * 64];

    const int tid = threadIdx.x;
    const int ty  = tid >> 4;
    const int tx  = tid & 15;
    const int m0  = blockIdx.x * 64;

    float acc[3][4][4];
#pragma unroll
    for (int w = 0; w < 3; w++)
#pragma unroll
        for (int i = 0; i < 4; i++)
#pragma unroll
            for (int j = 0; j < 4; j++) acc[w][i][j] = 0.0f;

    for (int kc = 0; kc < CC / 64; kc++) {
        __syncthreads();
#pragma unroll
        for (int i = 0; i < 4; i++) {
            int idx = i * 256 + tid;
            int r = idx >> 4, c4 = idx & 15;
            ((float4*)x_s)[idx] =
                *(const float4*)(x + (m0 + r) * CC + kc * 64 + c4 * 4);
        }
#pragma unroll
        for (int w = 0; w < 3; w++) {
            const float* W = (w == 0) ? Wq : (w == 1) ? Wk : Wv;
            __syncthreads();
            const float4* wt = (const float4*)(W + kc * 64 * HH);
#pragma unroll
            for (int i = 0; i < 4; i++) ((float4*)w_s)[i * 256 + tid] = wt[i * 256 + tid];
            __syncthreads();
#pragma unroll
            for (int k4 = 0; k4 < 16; k4++) {
                float a[4][4], bvv[4][4];
#pragma unroll
                for (int i = 0; i < 4; i++) {
                    float4 t = ((const float4*)x_s)[(ty * 4 + i) * 16 + k4];
                    a[i][0] = t.x; a[i][1] = t.y; a[i][2] = t.z; a[i][3] = t.w;
                }
#pragma unroll
                for (int c = 0; c < 4; c++) {
                    float4 t = ((const float4*)w_s)[(k4 * 4 + c) * 16 + tx];
                    bvv[c][0] = t.x; bvv[c][1] = t.y; bvv[c][2] = t.z; bvv[c][3] = t.w;
                }
#pragma unroll
                for (int i = 0; i < 4; i++)
#pragma unroll
                    for (int c = 0; c < 4; c++)
#pragma unroll
                        for (int j = 0; j < 4; j++)
                            acc[w][i][j] += a[i][c] * bvv[c][j];
            }
        }
    }

    float4 bqv = *(const float4*)(bq + tx * 4);
    float4 bkv = *(const float4*)(bk + tx * 4);
    float4 bvv4 = *(const float4*)(bv + tx * 4);
#pragma unroll
    for (int i = 0; i < 4; i++) {
        int row = m0 + ty * 4 + i;
        float4 r;
        r.x = acc[0][i][0] + bqv.x; r.y = acc[0][i][1] + bqv.y;
        r.z = acc[0][i][2] + bqv.z; r.w = acc[0][i][3] + bqv.w;
        *(float4*)(g_q + row * HH + tx * 4) = r;
        r.x = acc[1][i][0] + bkv.x; r.y = acc[1][i][1] + bkv.y;
        r.z = acc[1][i][2] + bkv.z; r.w = acc[1][i][3] + bkv.w;
        *(float4*)(g_k + row * HH + tx * 4) = r;
        r.x = acc[2][i][0] + bvv4.x; r.y = acc[2][i][1] + bvv4.y;
        r.z = acc[2][i][2] + bvv4.z; r.w = acc[2][i][3] + bvv4.w;
        *(float4*)(g_v + row * HH + tx * 4) = r;
    }
}

// ---------------------------------------------------------------------------
// Kernel 2: partial causal flash attention over key-chunks (split-K).
// Unit = (b, qt, chunk of up to 4 key-tiles). 128 threads: ty = tid>>4 (8 row
// groups of 8 rows), tx = tid&15 (4 keys / 4 d-cols). Thread tile 8x4.
// smem (dynamic, EXACTLY 48KB — no static smem, so the default per-block
// limit is respected): q_s[64x64], kp_s[64x64] (K^T then P), v_s[64x64].
// The scheduler broadcast slot aliases q_s[0]; an extra barrier orders the
// task-id read before the Q tile store overwrites it.
// ---------------------------------------------------------------------------
__global__ __launch_bounds__(128, 3) void attn_kernel(
    const unsigned char* __restrict__ pmask)
{
    extern __shared__ float smem[];
    float* q_s  = smem;             // [row][d]     16KB
    float* kp_s = smem + 4096;      // [d][key] -> [row][key] 16KB
    float* v_s  = smem + 8192;      // [key][d]    16KB
    int*   task_slot = (int*)smem;  // aliases q_s[0]

    const int tid = threadIdx.x;
    const int ty  = tid >> 4;       // 0..7
    const int tx  = tid & 15;       // 0..15

    while (true) {
        __syncthreads();            // all prior smem reads done; slot reusable
        if (tid == 0) *task_slot = atomicAdd(&g_ctr, 1);
        __syncthreads();
        int task = *task_slot;
        __syncthreads();            // everyone has read slot before Q store hits it
        if (task >= NUM_UNITS) break;

        // Serve units in reverse index order (large-qt chunks first).
        int u = NUM_UNITS - 1 - task;
        int b = u & 3;
        int t = u >> 2;                 // 0..543
        int g = 0;
#pragma unroll
        for (int gg = 1; gg < 16; gg++) if (2 * gg * (gg + 1) <= t) g = gg;
        int r  = t - 2 * g * (g + 1);
        int qt = 4 * g + r / (g + 1);
        int c  = r - (qt - 4 * g) * (g + 1);
        int kt0 = 4 * c;
        int kt1 = min(4 * c + 4, qt + 1);
        int sidx = b * UNITS_PER_B + t;   // scratch slot

        // load Q tile, pre-scaled by 1/sqrt(64)
        const float4* qb4 = (const float4*)(g_q + (b * TT + qt * 64) * HH);
#pragma unroll
        for (int i = 0; i < 8; i++) {
            float4 v = qb4[i * 128 + tid];
            v.x *= 0.125f; v.y *= 0.125f; v.z *= 0.125f; v.w *= 0.125f;
            ((float4*)q_s)[i * 128 + tid] = v;
        }

        float o[8][4];
        float m[8], l[8];
#pragma unroll
        for (int i = 0; i < 8; i++) {
            m[i] = NEG_BIG; l[i] = 0.0f;
#pragma unroll
            for (int j = 0; j < 4; j++) o[i][j] = 0.0f;
        }

        for (int kt = kt0; kt < kt1; kt++) {
            __syncthreads();  // prior tile reads (and q_s store) done

            // --- load K tile transposed into kp_s[d][key] ---
            {
                const float* kb = g_k + (b * TT + kt * 64) * HH;
                int kg = tid & 15;      // key group: keys kg*4..+3
                int dg = tid >> 4;      // d group:   dims dg*8..+7
                float t4[4][8];
#pragma unroll
                for (int rr = 0; rr < 4; rr++) {
                    float4 lo = *(const float4*)(kb + (kg * 4 + rr) * HH + dg * 8);
                    float4 hi = *(const float4*)(kb + (kg * 4 + rr) * HH + dg * 8 + 4);
                    t4[rr][0] = lo.x; t4[rr][1] = lo.y; t4[rr][2] = lo.z; t4[rr][3] = lo.w;
                    t4[rr][4] = hi.x; t4[rr][5] = hi.y; t4[rr][6] = hi.z; t4[rr][7] = hi.w;
                }
#pragma unroll
                for (int cc = 0; cc < 8; cc++) {
                    float4 col;
                    col.x = t4[0][cc]; col.y = t4[1][cc]; col.z = t4[2][cc]; col.w = t4[3][cc];
                    ((float4*)kp_s)[(dg * 8 + cc) * 16 + kg] = col;
                }
            }
            // --- load V tile ---
            {
                const float4* vb4 = (const float4*)(g_v + (b * TT + kt * 64) * HH);
#pragma unroll
                for (int i = 0; i < 8; i++)
                    ((float4*)v_s)[i * 128 + tid] = vb4[i * 128 + tid];
            }
            __syncthreads();

            // --- S = Q K^T ---
            float s[8][4];
#pragma unroll
            for (int i = 0; i < 8; i++)
#pragma unroll
                for (int j = 0; j < 4; j++) s[i][j] = 0.0f;
#pragma unroll
            for (int d4 = 0; d4 < 16; d4++) {
                float4 a[8];
#pragma unroll
                for (int i = 0; i < 8; i++)
                    a[i] = ((const float4*)q_s)[(ty * 8 + i) * 16 + d4];
#pragma unroll
                for (int cc = 0; cc < 4; cc++) {
                    float4 kv = ((const float4*)kp_s)[(d4 * 4 + cc) * 16 + tx];
                    const float* ap;
#pragma unroll
                    for (int i = 0; i < 8; i++) {
                        ap = (const float*)&a[i];
                        float av = ap[cc];
                        s[i][0] += av * kv.x;
                        s[i][1] += av * kv.y;
                        s[i][2] += av * kv.z;
                        s[i][3] += av * kv.w;
                    }
                }
            }

            // --- padding mask over keys ---
            {
                uchar4 pm = *(const uchar4*)(pmask + b * TT + kt * 64 + tx * 4);
                unsigned char pb[4] = {pm.x, pm.y, pm.z, pm.w};
#pragma unroll
                for (int j = 0; j < 4; j++)
                    if (pb[j]) {
#pragma unroll
                        for (int i = 0; i < 8; i++) s[i][j] = NEG_BIG;
                    }
            }
            // --- causal mask (diagonal tile only) ---
            if (kt == qt) {
#pragma unroll
                for (int i = 0; i < 8; i++)
#pragma unroll
                    for (int j = 0; j < 4; j++)
                        if (tx * 4 + j > ty * 8 + i) s[i][j] = NEG_BIG;
            }

            // --- online softmax update (row reduce across 16 tx lanes) ---
#pragma unroll
            for (int i = 0; i < 8; i++) {
                float mx = fmaxf(fmaxf(s[i][0], s[i][1]), fmaxf(s[i][2], s[i][3]));
                mx = fmaxf(mx, __shfl_xor_sync(0xffffffffu, mx, 1));
                mx = fmaxf(mx, __shfl_xor_sync(0xffffffffu, mx, 2));
                mx = fmaxf(mx, __shfl_xor_sync(0xffffffffu, mx, 4));
                mx = fmaxf(mx, __shfl_xor_sync(0xffffffffu, mx, 8));
                float mn = fmaxf(m[i], mx);
                float alpha = __expf(m[i] - mn);
                m[i] = mn;
                float ps = 0.0f;
#pragma unroll
                for (int j = 0; j < 4; j++) {
                    float p = __expf(s[i][j] - mn);
                    s[i][j] = p;
                    ps += p;
                }
                ps += __shfl_xor_sync(0xffffffffu, ps, 1);
                ps += __shfl_xor_sync(0xffffffffu, ps, 2);
                ps += __shfl_xor_sync(0xffffffffu, ps, 4);
                ps += __shfl_xor_sync(0xffffffffu, ps, 8);
                l[i] = l[i] * alpha + ps;
#pragma unroll
                for (int j = 0; j < 4; j++) o[i][j] *= alpha;
            }

            __syncthreads();  // all GEMM1 reads of kp_s done
            // --- store P into kp_s [row][key] ---
#pragma unroll
            for (int i = 0; i < 8; i++) {
                float4 tt;
                tt.x = s[i][0]; tt.y = s[i][1]; tt.z = s[i][2]; tt.w = s[i][3];
                ((float4*)kp_s)[(ty * 8 + i) * 16 + tx] = tt;
            }
            __syncthreads();

            // --- O += P @ V ---
#pragma unroll
            for (int n4 = 0; n4 < 16; n4++) {
                float4 p[8];
#pragma unroll
                for (int i = 0; i < 8; i++)
                    p[i] = ((const float4*)kp_s)[(ty * 8 + i) * 16 + n4];
#pragma unroll
                for (int cc = 0; cc < 4; cc++) {
                    float4 vv = ((const float4*)v_s)[(n4 * 4 + cc) * 16 + tx];
                    const float* pp;
#pragma unroll
                    for (int i = 0; i < 8; i++) {
                        pp = (const float*)&p[i];
                        float pv = pp[cc];
                        o[i][0] += pv * vv.x;
                        o[i][1] += pv * vv.y;
                        o[i][2] += pv * vv.z;
                        o[i][3] += pv * vv.w;
                    }
                }
            }
        }

        // --- write partial result (unnormalized) ---
        float* pOb = g_pO + sidx * 64 * 64;
#pragma unroll
        for (int i = 0; i < 8; i++) {
            float4 rr;
            rr.x = o[i][0]; rr.y = o[i][1]; rr.z = o[i][2]; rr.w = o[i][3];
            ((float4*)pOb)[(ty * 8 + i) * 16 + tx] = rr;
        }
        if (tx == 0) {
#pragma unroll
            for (int i = 0; i < 8; i++) {
                g_pm[sidx * 64 + ty * 8 + i] = m[i];
                g_pl[sidx * 64 + ty * 8 + i] = l[i];
            }
        }
    }
}

// ---------------------------------------------------------------------------
// Kernel 3: merge partials per (b, qt). grid = 256 blocks, 256 threads.
// Thread handles one row x 16 cols (4 float4).
// ---------------------------------------------------------------------------
__global__ __launch_bounds__(256) void merge_kernel(float* __restrict__ out)
{
    int qt = blockIdx.x >> 2;
    int b  = blockIdx.x & 3;
    int g  = qt >> 2;
    int tb = 2 * g * (g + 1) + (qt - 4 * g) * (g + 1);
    int nch = g + 1;
    int base = b * UNITS_PER_B + tb;

    int row = threadIdx.x >> 2;      // 0..63
    int qd  = threadIdx.x & 3;       // col group of 16

    // global max across chunks
    float M = NEG_BIG;
    for (int c = 0; c < nch; c++)
        M = fmaxf(M, g_pm[(base + c) * 64 + row]);

    float L = 0.0f;
    float4 a0 = {0,0,0,0}, a1 = {0,0,0,0}, a2 = {0,0,0,0}, a3 = {0,0,0,0};
    for (int c = 0; c < nch; c++) {
        int s = base + c;
        float w = __expf(g_pm[s * 64 + row] - M);
        L += g_pl[s * 64 + row] * w;
        const float4* po = (const float4*)(g_pO + (s * 64 + row) * 64) + qd * 4;
        float4 v0 = po[0], v1 = po[1], v2 = po[2], v3 = po[3];
        a0.x += w * v0.x; a0.y += w * v0.y; a0.z += w * v0.z; a0.w += w * v0.w;
        a1.x += w * v1.x; a1.y += w * v1.y; a1.z += w * v1.z; a1.w += w * v1.w;
        a2.x += w * v2.x; a2.y += w * v2.y; a2.z += w * v2.z; a2.w += w * v2.w;
        a3.x += w * v3.x; a3.y += w * v3.y; a3.z += w * v3.z; a3.w += w * v3.w;
    }
    float inv = 1.0f / L;
    a0.x *= inv; a0.y *= inv; a0.z *= inv; a0.w *= inv;
    a1.x *= inv; a1.y *= inv; a1.z *= inv; a1.w *= inv;
    a2.x *= inv; a2.y *= inv; a2.z *= inv; a2.w *= inv;
    a3.x *= inv; a3.y *= inv; a3.z *= inv; a3.w *= inv;

    float4* ob = (float4*)(out + (b * TT + qt * 64 + row) * HH) + qd * 4;
    ob[0] = a0; ob[1] = a1; ob[2] = a2; ob[3] = a3;
}

// ---------------------------------------------------------------------------
extern "C" void kernel_launch(void* const* d_in, const int* in_sizes, int n_in,
                              void* d_out, int out_size)
{
    const float*         x     = (const float*)d_in[0];
    const unsigned char* pmask = (const unsigned char*)d_in[1];
    const float*         Wq    = (const float*)d_in[2];
    const float*         bq    = (const float*)d_in[3];
    const float*         Wk    = (const float*)d_in[4];
    const float*         bk    = (const float*)d_in[5];
    const float*         Wv    = (const float*)d_in[6];
    const float*         bv    = (const float*)d_in[7];

    proj_kernel<<<(BB * TT) / 64, 256>>>(x, Wq, bq, Wk, bk, Wv, bv);
    attn_kernel<<<444, 128, 49152>>>(pmask);
    merge_kernel<<<256, 256>>>((float*)d_out);
}

// round 8
// speedup vs baseline: 1.8672x; 1.0254x over previous
#include <cuda_runtime.h>

#define BB 4
#define TT 4096
#define CC 512
#define HH 64

#define NEG_BIG (-1e30f)

// Units: chunk = up to 4 key-tiles (256 keys). Per batch: sum_qt (qt/4+1) = 544.
#define UNITS_PER_B 544
#define NUM_UNITS   (UNITS_PER_B * BB)   // 2176

#define KPAD 68   // padded row length (floats) for k/vT smem buffer

// Scratch
__device__ float g_q[BB * TT * HH];
__device__ float g_k[BB * TT * HH];
__device__ float g_v[BB * TT * HH];
__device__ float g_pO[NUM_UNITS * 64 * 64];   // partial (unnormalized) O
__device__ float g_pm[NUM_UNITS * 64];        // partial row max
__device__ float g_pl[NUM_UNITS * 64];        // partial row sum
__device__ int   g_ctr;

// ---- packed f32x2 helpers (Blackwell FFMA2 path) ---------------------------
typedef unsigned long long u64t;

union F4U2 { float4 f4; u64t u2[2]; };

__device__ __forceinline__ void ffma2(u64t& d, u64t a, u64t b) {
    asm("fma.rn.f32x2 %0, %1, %2, %3;" : "=l"(d) : "l"(a), "l"(b), "l"(d));
}
__device__ __forceinline__ u64t mul2(u64t a, u64t b) {
    u64t r; asm("mul.rn.f32x2 %0, %1, %2;" : "=l"(r) : "l"(a), "l"(b)); return r;
}
__device__ __forceinline__ u64t pack2(float a, float b) {
    u64t r; asm("mov.b64 %0, {%1, %2};" : "=l"(r) : "f"(a), "f"(b)); return r;
}
__device__ __forceinline__ float fold2(u64t v) {
    float lo, hi; asm("mov.b64 {%0, %1}, %2;" : "=f"(lo), "=f"(hi) : "l"(v));
    return lo + hi;
}

// ---------------------------------------------------------------------------
// Kernel 1: fused QKV projection. q is pre-scaled by 1/sqrt(H)=0.125 on store.
// ---------------------------------------------------------------------------
__global__ __launch_bounds__(256) void proj_kernel(
    const float* __restrict__ x,
    const float* __restrict__ Wq, const float* __restrict__ bq,
    const float* __restrict__ Wk, const float* __restrict__ bk,
    const float* __restrict__ Wv, const float* __restrict__ bv)
{
    if (blockIdx.x == 0 && threadIdx.x == 0) g_ctr = 0;  // reset scheduler

    __shared__ float x_s[64 * 64];
    __shared__ float w_s[64 * 64];

    const int tid = threadIdx.x;
    const int ty  = tid >> 4;
    const int tx  = tid & 15;
    const int m0  = blockIdx.x * 64;

    float acc[3][4][4];
#pragma unroll
    for (int w = 0; w < 3; w++)
#pragma unroll
        for (int i = 0; i < 4; i++)
#pragma unroll
            for (int j = 0; j < 4; j++) acc[w][i][j] = 0.0f;

    for (int kc = 0; kc < CC / 64; kc++) {
        __syncthreads();
#pragma unroll
        for (int i = 0; i < 4; i++) {
            int idx = i * 256 + tid;
            int r = idx >> 4, c4 = idx & 15;
            ((float4*)x_s)[idx] =
                *(const float4*)(x + (m0 + r) * CC + kc * 64 + c4 * 4);
        }
#pragma unroll
        for (int w = 0; w < 3; w++) {
            const float* W = (w == 0) ? Wq : (w == 1) ? Wk : Wv;
            __syncthreads();
            const float4* wt = (const float4*)(W + kc * 64 * HH);
#pragma unroll
            for (int i = 0; i < 4; i++) ((float4*)w_s)[i * 256 + tid] = wt[i * 256 + tid];
            __syncthreads();
#pragma unroll
            for (int k4 = 0; k4 < 16; k4++) {
                float a[4][4], bvv[4][4];
#pragma unroll
                for (int i = 0; i < 4; i++) {
                    float4 t = ((const float4*)x_s)[(ty * 4 + i) * 16 + k4];
                    a[i][0] = t.x; a[i][1] = t.y; a[i][2] = t.z; a[i][3] = t.w;
                }
#pragma unroll
                for (int c = 0; c < 4; c++) {
                    float4 t = ((const float4*)w_s)[(k4 * 4 + c) * 16 + tx];
                    bvv[c][0] = t.x; bvv[c][1] = t.y; bvv[c][2] = t.z; bvv[c][3] = t.w;
                }
#pragma unroll
                for (int i = 0; i < 4; i++)
#pragma unroll
                    for (int c = 0; c < 4; c++)
#pragma unroll
                        for (int j = 0; j < 4; j++)
                            acc[w][i][j] += a[i][c] * bvv[c][j];
            }
        }
    }

    float4 bqv = *(const float4*)(bq + tx * 4);
    float4 bkv = *(const float4*)(bk + tx * 4);
    float4 bvv4 = *(const float4*)(bv + tx * 4);
#pragma unroll
    for (int i = 0; i < 4; i++) {
        int row = m0 + ty * 4 + i;
        float4 r;
        // q pre-scaled by 1/sqrt(64)
        r.x = (acc[0][i][0] + bqv.x) * 0.125f; r.y = (acc[0][i][1] + bqv.y) * 0.125f;
        r.z = (acc[0][i][2] + bqv.z) * 0.125f; r.w = (acc[0][i][3] + bqv.w) * 0.125f;
        *(float4*)(g_q + row * HH + tx * 4) = r;
        r.x = acc[1][i][0] + bkv.x; r.y = acc[1][i][1] + bkv.y;
        r.z = acc[1][i][2] + bkv.z; r.w = acc[1][i][3] + bkv.w;
        *(float4*)(g_k + row * HH + tx * 4) = r;
        r.x = acc[2][i][0] + bvv4.x; r.y = acc[2][i][1] + bvv4.y;
        r.z = acc[2][i][2] + bvv4.z; r.w = acc[2][i][3] + bvv4.w;
        *(float4*)(g_v + row * HH + tx * 4) = r;
    }
}

// ---------------------------------------------------------------------------
// Kernel 2: split-K flash attention with packed-f32x2 (FFMA2) GEMMs.
// 128 threads: ty=tid>>4 (8 row-groups of 8), tx=tid&15. Thread outputs:
// rows ty*8..+7, cols {tx, tx+16, tx+32, tx+48}.
// Both GEMMs reduce along a CONTIGUOUS smem dim -> operands pair-packable
// with zero pack instructions (float4 load = two 64-bit halves).
// smem 33792B: qp_s[64][64] (Q, then P), kv_s[64][KPAD] (K natural, then vT).
// Q is reloaded from g_q each key-tile so P can overwrite it.
// ---------------------------------------------------------------------------
__global__ __launch_bounds__(128, 3) void attn_kernel(
    const unsigned char* __restrict__ pmask)
{
    extern __shared__ float smem[];
    float* qp_s = smem;             // [row][d] = Q, then [row][key] = P   16KB
    float* kv_s = smem + 4096;      // [key][KPAD] = K, then [d][KPAD] = vT 17408B
    int*   task_slot = (int*)smem;  // aliases qp_s[0]

    const int tid = threadIdx.x;
    const int ty  = tid >> 4;       // 0..7
    const int tx  = tid & 15;       // 0..15

    while (true) {
        __syncthreads();            // all prior smem reads done; slot reusable
        if (tid == 0) *task_slot = atomicAdd(&g_ctr, 1);
        __syncthreads();
        int task = *task_slot;
        __syncthreads();            // slot read before any smem store hits it
        if (task >= NUM_UNITS) break;

        // Serve units in reverse index order (large-qt chunks first).
        int u = NUM_UNITS - 1 - task;
        int b = u & 3;
        int t = u >> 2;                 // 0..543
        int g = 0;
#pragma unroll
        for (int gg = 1; gg < 16; gg++) if (2 * gg * (gg + 1) <= t) g = gg;
        int r  = t - 2 * g * (g + 1);
        int qt = 4 * g + r / (g + 1);
        int c  = r - (qt - 4 * g) * (g + 1);
        int kt0 = 4 * c;
        int kt1 = min(4 * c + 4, qt + 1);
        int sidx = b * UNITS_PER_B + t;   // scratch slot

        u64t o2[8][4];                   // packed O accumulators (persist over tiles)
        float m[8], l[8];
#pragma unroll
        for (int i = 0; i < 8; i++) {
            m[i] = NEG_BIG; l[i] = 0.0f;
#pragma unroll
            for (int j = 0; j < 4; j++) o2[i][j] = 0ull;
        }

        const float4* qb4 = (const float4*)(g_q + (b * TT + qt * 64) * HH);

        for (int kt = kt0; kt < kt1; kt++) {
            __syncthreads();  // prior tile's PV reads (P in qp_s, vT in kv_s) done

            // --- (re)load Q tile (pre-scaled in proj) into qp_s ---
#pragma unroll
            for (int i = 0; i < 8; i++)
                ((float4*)qp_s)[i * 128 + tid] = qb4[i * 128 + tid];

            // --- load K tile in NATURAL [key][d] layout, rows padded to KPAD ---
            {
                const float4* kb4 = (const float4*)(g_k + (b * TT + kt * 64) * HH);
#pragma unroll
                for (int i = 0; i < 8; i++) {
                    int idx = i * 128 + tid;
                    int key = idx >> 4, qd = idx & 15;
                    *(float4*)(kv_s + key * KPAD + qd * 4) = kb4[idx];
                }
            }
            __syncthreads();

            // --- S = Q K^T, packed over d-pairs ---
            u64t s2[8][4];
#pragma unroll
            for (int i = 0; i < 8; i++)
#pragma unroll
                for (int j = 0; j < 4; j++) s2[i][j] = 0ull;

#pragma unroll
            for (int d4 = 0; d4 < 16; d4++) {
                F4U2 qv[8], kv[4];
#pragma unroll
                for (int i = 0; i < 8; i++)
                    qv[i].f4 = ((const float4*)qp_s)[(ty * 8 + i) * 16 + d4];
#pragma unroll
                for (int j = 0; j < 4; j++)
                    kv[j].f4 = *(const float4*)(kv_s + (tx + 16 * j) * KPAD + d4 * 4);
#pragma unroll
                for (int i = 0; i < 8; i++)
#pragma unroll
                    for (int j = 0; j < 4; j++) {
                        ffma2(s2[i][j], qv[i].u2[0], kv[j].u2[0]);
                        ffma2(s2[i][j], qv[i].u2[1], kv[j].u2[1]);
                    }
            }

            // fold halves
            float s[8][4];
#pragma unroll
            for (int i = 0; i < 8; i++)
#pragma unroll
                for (int j = 0; j < 4; j++) s[i][j] = fold2(s2[i][j]);

            // --- padding mask over keys (key index = tx + 16j) ---
#pragma unroll
            for (int j = 0; j < 4; j++) {
                if (pmask[b * TT + kt * 64 + tx + 16 * j]) {
#pragma unroll
                    for (int i = 0; i < 8; i++) s[i][j] = NEG_BIG;
                }
            }
            // --- causal mask (diagonal tile only) ---
            if (kt == qt) {
#pragma unroll
                for (int i = 0; i < 8; i++)
#pragma unroll
                    for (int j = 0; j < 4; j++)
                        if (tx + 16 * j > ty * 8 + i) s[i][j] = NEG_BIG;
            }

            // --- online softmax update (row reduce across 16 tx lanes) ---
#pragma unroll
            for (int i = 0; i < 8; i++) {
                float mx = fmaxf(fmaxf(s[i][0], s[i][1]), fmaxf(s[i][2], s[i][3]));
                mx = fmaxf(mx, __shfl_xor_sync(0xffffffffu, mx, 1));
                mx = fmaxf(mx, __shfl_xor_sync(0xffffffffu, mx, 2));
                mx = fmaxf(mx, __shfl_xor_sync(0xffffffffu, mx, 4));
                mx = fmaxf(mx, __shfl_xor_sync(0xffffffffu, mx, 8));
                float mn = fmaxf(m[i], mx);
                float alpha = __expf(m[i] - mn);
                m[i] = mn;
                float ps = 0.0f;
#pragma unroll
                for (int j = 0; j < 4; j++) {
                    float p = __expf(s[i][j] - mn);
                    s[i][j] = p;
                    ps += p;
                }
                ps += __shfl_xor_sync(0xffffffffu, ps, 1);
                ps += __shfl_xor_sync(0xffffffffu, ps, 2);
                ps += __shfl_xor_sync(0xffffffffu, ps, 4);
                ps += __shfl_xor_sync(0xffffffffu, ps, 8);
                l[i] = l[i] * alpha + ps;
                u64t a2 = pack2(alpha, alpha);
#pragma unroll
                for (int j = 0; j < 4; j++) o2[i][j] = mul2(o2[i][j], a2);
            }

            __syncthreads();  // all S-GEMM reads of qp_s/kv_s done

            // --- store P into qp_s [row][key] (overwrites Q) ---
#pragma unroll
            for (int i = 0; i < 8; i++)
#pragma unroll
                for (int j = 0; j < 4; j++)
                    qp_s[(ty * 8 + i) * 64 + tx + 16 * j] = s[i][j];

            // --- load V TRANSPOSED into kv_s: vT[d][key], rows padded KPAD ---
            {
                const float* vb = g_v + (b * TT + kt * 64) * HH;
                int kg = tid & 15;   // key group: keys kg*4..+3
                int dg = tid >> 4;   // d group:   dims dg*8..+7
                float t4[4][8];
#pragma unroll
                for (int rr = 0; rr < 4; rr++) {
                    float4 lo = *(const float4*)(vb + (kg * 4 + rr) * HH + dg * 8);
                    float4 hi = *(const float4*)(vb + (kg * 4 + rr) * HH + dg * 8 + 4);
                    t4[rr][0] = lo.x; t4[rr][1] = lo.y; t4[rr][2] = lo.z; t4[rr][3] = lo.w;
                    t4[rr][4] = hi.x; t4[rr][5] = hi.y; t4[rr][6] = hi.z; t4[rr][7] = hi.w;
                }
#pragma unroll
                for (int cc = 0; cc < 8; cc++) {
                    float4 col;
                    col.x = t4[0][cc]; col.y = t4[1][cc]; col.z = t4[2][cc]; col.w = t4[3][cc];
                    *(float4*)(kv_s + (dg * 8 + cc) * KPAD + kg * 4) = col;
                }
            }
            __syncthreads();

            // --- O += P @ V, packed over key-pairs ---
#pragma unroll
            for (int k4 = 0; k4 < 16; k4++) {
                F4U2 pv[8], vv[4];
#pragma unroll
                for (int i = 0; i < 8; i++)
                    pv[i].f4 = ((const float4*)qp_s)[(ty * 8 + i) * 16 + k4];
#pragma unroll
                for (int j = 0; j < 4; j++)
                    vv[j].f4 = *(const float4*)(kv_s + (tx + 16 * j) * KPAD + k4 * 4);
#pragma unroll
                for (int i = 0; i < 8; i++)
#pragma unroll
                    for (int j = 0; j < 4; j++) {
                        ffma2(o2[i][j], pv[i].u2[0], vv[j].u2[0]);
                        ffma2(o2[i][j], pv[i].u2[1], vv[j].u2[1]);
                    }
            }
        }

        // --- write partial result (unnormalized); out col = tx + 16j ---
        float* pOb = g_pO + sidx * 64 * 64;
#pragma unroll
        for (int i = 0; i < 8; i++)
#pragma unroll
            for (int j = 0; j < 4; j++)
                pOb[(ty * 8 + i) * 64 + tx + 16 * j] = fold2(o2[i][j]);
        if (tx == 0) {
#pragma unroll
            for (int i = 0; i < 8; i++) {
                g_pm[sidx * 64 + ty * 8 + i] = m[i];
                g_pl[sidx * 64 + ty * 8 + i] = l[i];
            }
        }
    }
}

// ---------------------------------------------------------------------------
// Kernel 3: merge partials per (b, qt). grid = 256 blocks, 256 threads.
// ---------------------------------------------------------------------------
__global__ __launch_bounds__(256) void merge_kernel(float* __restrict__ out)
{
    int qt = blockIdx.x >> 2;
    int b  = blockIdx.x & 3;
    int g  = qt >> 2;
    int tb = 2 * g * (g + 1) + (qt - 4 * g) * (g + 1);
    int nch = g + 1;
    int base = b * UNITS_PER_B + tb;

    int row = threadIdx.x >> 2;      // 0..63
    int qd  = threadIdx.x & 3;       // col group of 16

    float M = NEG_BIG;
    for (int c = 0; c < nch; c++)
        M = fmaxf(M, g_pm[(base + c) * 64 + row]);

    float L = 0.0f;
    float4 a0 = {0,0,0,0}, a1 = {0,0,0,0}, a2 = {0,0,0,0}, a3 = {0,0,0,0};
    for (int c = 0; c < nch; c++) {
        int s = base + c;
        float w = __expf(g_pm[s * 64 + row] - M);
        L += g_pl[s * 64 + row] * w;
        const float4* po = (const float4*)(g_pO + (s * 64 + row) * 64) + qd * 4;
        float4 v0 = po[0], v1 = po[1], v2 = po[2], v3 = po[3];
        a0.x += w * v0.x; a0.y += w * v0.y; a0.z += w * v0.z; a0.w += w * v0.w;
        a1.x += w * v1.x; a1.y += w * v1.y; a1.z += w * v1.z; a1.w += w * v1.w;
        a2.x += w * v2.x; a2.y += w * v2.y; a2.z += w * v2.z; a2.w += w * v2.w;
        a3.x += w * v3.x; a3.y += w * v3.y; a3.z += w * v3.z; a3.w += w * v3.w;
    }
    float inv = 1.0f / L;
    a0.x *= inv; a0.y *= inv; a0.z *= inv; a0.w *= inv;
    a1.x *= inv; a1.y *= inv; a1.z *= inv; a1.w *= inv;
    a2.x *= inv; a2.y *= inv; a2.z *= inv; a2.w *= inv;
    a3.x *= inv; a3.y *= inv; a3.z *= inv; a3.w *= inv;

    float4* ob = (float4*)(out + (b * TT + qt * 64 + row) * HH) + qd * 4;
    ob[0] = a0; ob[1] = a1; ob[2] = a2; ob[3] = a3;
}

// ---------------------------------------------------------------------------
extern "C" void kernel_launch(void* const* d_in, const int* in_sizes, int n_in,
                              void* d_out, int out_size)
{
    const float*         x     = (const float*)d_in[0];
    const unsigned char* pmask = (const unsigned char*)d_in[1];
    const float*         Wq    = (const float*)d_in[2];
    const float*         bq    = (const float*)d_in[3];
    const float*         Wk    = (const float*)d_in[4];
    const float*         bk    = (const float*)d_in[5];
    const float*         Wv    = (const float*)d_in[6];
    const float*         bv    = (const float*)d_in[7];

    proj_kernel<<<(BB * TT) / 64, 256>>>(x, Wq, bq, Wk, bk, Wv, bv);
    attn_kernel<<<444, 128, 33792>>>(pmask);
    merge_kernel<<<256, 256>>>((float*)d_out);
}